// round 14
// baseline (speedup 1.0000x reference)
#include <cuda_runtime.h>

// Problem constants (fixed shapes for this problem)
#define NEDGE 160000

// Scratch (static device arrays — cudaMalloc is forbidden)
__device__ __align__(16) float g_T[972];   // T[(a*9+b)*12 + d], pad 12

typedef unsigned long long u64;

// ---------------------------------------------------------------------------
// packed f32x2 helpers (Blackwell FFMA2)
// ---------------------------------------------------------------------------
__device__ __forceinline__ u64 pk2(float x, float y) {
    u64 r; asm("mov.b64 %0, {%1, %2};" : "=l"(r) : "f"(x), "f"(y)); return r;
}
__device__ __forceinline__ void up2(u64 v, float& x, float& y) {
    asm("mov.b64 {%0, %1}, %2;" : "=f"(x), "=f"(y) : "l"(v));
}
__device__ __forceinline__ u64 ffma2(u64 a, u64 b, u64 c) {
    u64 d; asm("fma.rn.f32x2 %0, %1, %2, %3;" : "=l"(d) : "l"(a), "l"(b), "l"(c));
    return d;
}
__device__ __forceinline__ u64 mul2(u64 a, u64 b) {
    u64 d; asm("mul.rn.f32x2 %0, %1, %2;" : "=l"(d) : "l"(a), "l"(b));
    return d;
}

__device__ __forceinline__ float sspf(float x) {
    float e = __expf(-fabsf(x));
    return fmaxf(x, 0.0f) + __logf(1.0f + e) - 0.69314718055994531f;
}

// ---------------------------------------------------------------------------
// gridval: real 9x9 grid value of one spherical basis vector through
// pad -> ifftshift -> truncate -> irfft2 (numpy Im(DC)-dropped convention)
// ---------------------------------------------------------------------------
__device__ __forceinline__ float gridval(const float* __restrict__ Ur,
                                         const float* __restrict__ Ui,
                                         int a, int s, int t,
                                         const float* C, const float* S) {
    float acc = 0.0f;
    #pragma unroll
    for (int v = 0; v < 5; v++) {
        float gr = 0.0f, gi = 0.0f;
        int jj = (v + 4) % 9 - 2;                 // padded col -> U col
        if (jj >= 0 && jj < 5) {
            #pragma unroll
            for (int u = 0; u < 9; u++) {
                int ii = (u + 4) % 9 - 2;         // padded row -> U row
                if (ii >= 0 && ii < 5) {
                    float cr = Ur[a * 25 + ii * 5 + jj];
                    float ci = Ui[a * 25 + ii * 5 + jj];
                    int k = (u * s) % 9;
                    gr += cr * C[k] - ci * S[k];
                    gi += cr * S[k] + ci * C[k];
                }
            }
        }
        if (v == 0) {
            acc += gr;                             // Im(DC) dropped
        } else {
            int k2 = (v * t) % 9;
            acc += 2.0f * (gr * C[k2] - gi * S[k2]);
        }
    }
    return acc * (1.0f / 81.0f);
}

// ---------------------------------------------------------------------------
// kprep: all blocks zero the output; block 0 additionally builds T.
// ---------------------------------------------------------------------------
__global__ void __launch_bounds__(256) kprep(
    const float* __restrict__ Uxr, const float* __restrict__ Uxi,
    const float* __restrict__ Ufr, const float* __restrict__ Ufi,
    const float* __restrict__ Vr,  const float* __restrict__ Vi,
    const float* __restrict__ denom,
    float4* __restrict__ o4, int n4) {
    __shared__ float C9[9], S9[9];
    __shared__ float Gx[729], Gf[729], Pm[729];

    int tid = threadIdx.x;
    int i = blockIdx.x * 256 + tid;
    if (i < n4) o4[i] = make_float4(0.f, 0.f, 0.f, 0.f);

    if (blockIdx.x != 0) return;

    if (tid < 9) {
        double ang = 2.0 * 3.14159265358979323846 * (double)tid / 9.0;
        C9[tid] = (float)cos(ang);
        S9[tid] = (float)sin(ang);
    }
    __syncthreads();
    for (int idx = tid; idx < 729; idx += 256) {
        {   // grid bases: idx = a*81 + s*9 + t
            int a = idx / 81, s = (idx / 9) % 9, t = idx % 9;
            Gx[idx] = gridval(Uxr, Uxi, a, s, t, C9, S9);
            Gf[idx] = gridval(Ufr, Ufi, a, s, t, C9, S9);
        }
        {   // projection: idx = (s*9+t)*9 + d
            int st = idx / 9, d = idx % 9;
            int s = st / 9, t = st % 9;
            float p = 0.0f;
            #pragma unroll
            for (int u = 0; u < 9; u++)
                #pragma unroll
                for (int k = 0; k < 5; k++) {
                    int th = (u * s + k * t) % 9;
                    p += Vr[u * 45 + k * 9 + d] * C9[th]
                       + Vi[u * 45 + k * 9 + d] * S9[th];
                }
            Pm[idx] = p;
        }
    }
    __syncthreads();
    float inv = 1.0f / denom[0];
    for (int idx = tid; idx < 729; idx += 256) {
        int a = idx / 81, b = (idx / 9) % 9, d = idx % 9;
        float acc = 0.0f;
        #pragma unroll 9
        for (int st = 0; st < 81; st++)
            acc += Gx[a * 81 + st] * Gf[b * 81 + st] * Pm[st * 9 + d];
        g_T[(a * 9 + b) * 12 + d] = acc * inv;
    }
}

// ---------------------------------------------------------------------------
// kfuse: fused block-tiled MLP + message + scatter. 128 threads = 128 edges.
//   MLP identical to R12 (block-tiled GEMM form).
//   Bridge wst and per-warp fbuf both use granule-rotation swizzles; rotation
//   keys are PRE-REDUCED mod 13 so the in-loop single conditional subtract is
//   an exact mod (R13's bug: keys up to 45 overflowed one subtract).
//   Message math packed in f32x2 (d-pairs), results streamed as scalar
//   swizzled STS.
// ---------------------------------------------------------------------------
#define POOL_FLOATS 15872
#define BUF_OFF 7680
#define FBUF_OFF 6656

__global__ void __launch_bounds__(128, 3) kfuse(
    const float* __restrict__ win,
    const float* __restrict__ fsph,
    const int*   __restrict__ eidx,
    const float* __restrict__ W1,
    const float* __restrict__ W2,
    const float* __restrict__ W3,
    const float* __restrict__ aw,
    const float* __restrict__ x,
    float* __restrict__ out,
    int E) {
    extern __shared__ __align__(16) float pool[];
    __shared__ __align__(16) float Tsh[972];
    __shared__ __align__(16) float awp[36];   // a_w padded rows of 12

    const int tid  = threadIdx.x;
    const int wid  = tid >> 5;
    const int lane = tid & 31;

    // ---- stage weights (coalesced, once per block) + T + aw(padded) ----
    float4* p4 = (float4*)pool;
    p4[tid] = ((const float4*)W1)[tid];                       // 512 f @ 0
    #pragma unroll
    for (int i = 0; i < 8; i++)                               // 4096 f @ 512
        p4[128 + tid + i * 128] = ((const float4*)W2)[tid + i * 128];
    #pragma unroll
    for (int i = 0; i < 6; i++)                               // 3072 f @ 4608
        p4[1152 + tid + i * 128] = ((const float4*)W3)[tid + i * 128];
    #pragma unroll
    for (int i = 0; i < 8; i++) {
        int idx = tid + i * 128;
        if (idx < 972) Tsh[idx] = g_T[idx];
    }
    if (tid < 27) awp[(tid / 9) * 12 + (tid % 9)] = aw[tid];

    // ---- per-thread message-edge metadata + win -> wiT (buf rows 0..7) ----
    int e = blockIdx.x * 128 + tid;
    int valid = (e < E) ? 1 : 0;
    int ec = valid ? e : 0;
    int dst = __ldg(&eidx[ec]);
    int src = __ldg(&eidx[E + ec]);

    float* buf = pool + BUF_OFF;
    {
        float4 wa = __ldg(&((const float4*)win)[(size_t)ec * 2 + 0]);
        float4 wb = __ldg(&((const float4*)win)[(size_t)ec * 2 + 1]);
        buf[0 * 128 + tid] = wa.x; buf[1 * 128 + tid] = wa.y;
        buf[2 * 128 + tid] = wa.z; buf[3 * 128 + tid] = wa.w;
        buf[4 * 128 + tid] = wb.x; buf[5 * 128 + tid] = wb.y;
        buf[6 * 128 + tid] = wb.z; buf[7 * 128 + tid] = wb.w;
    }
    __syncthreads();

    const ulonglong2* w1u = (const ulonglong2*)pool;            // 128 u2
    const ulonglong2* w2u = (const ulonglong2*)(pool + 512);    // 1024 u2
    const ulonglong2* w3u = (const ulonglong2*)(pool + 4608);   // 768 u2

    u64 acc[32];        // [4 edges][8 outpairs]
    float hr[64];       // [4 edges][16 outs]

    // ----- layer 1: outs [wid*16, +16), edges lane*4..+3 -----
    #pragma unroll
    for (int t = 0; t < 32; t++) acc[t] = 0ull;
    #pragma unroll
    for (int i = 0; i < 8; i++) {
        float4 hv = *(const float4*)&buf[i * 128 + lane * 4];
        u64 h0 = pk2(hv.x, hv.x), h1 = pk2(hv.y, hv.y);
        u64 h2 = pk2(hv.z, hv.z), h3 = pk2(hv.w, hv.w);
        #pragma unroll
        for (int q = 0; q < 4; q++) {
            ulonglong2 wq = w1u[i * 16 + wid * 4 + q];
            acc[0 * 8 + 2 * q + 0] = ffma2(h0, wq.x, acc[0 * 8 + 2 * q + 0]);
            acc[0 * 8 + 2 * q + 1] = ffma2(h0, wq.y, acc[0 * 8 + 2 * q + 1]);
            acc[1 * 8 + 2 * q + 0] = ffma2(h1, wq.x, acc[1 * 8 + 2 * q + 0]);
            acc[1 * 8 + 2 * q + 1] = ffma2(h1, wq.y, acc[1 * 8 + 2 * q + 1]);
            acc[2 * 8 + 2 * q + 0] = ffma2(h2, wq.x, acc[2 * 8 + 2 * q + 0]);
            acc[2 * 8 + 2 * q + 1] = ffma2(h2, wq.y, acc[2 * 8 + 2 * q + 1]);
            acc[3 * 8 + 2 * q + 0] = ffma2(h3, wq.x, acc[3 * 8 + 2 * q + 0]);
            acc[3 * 8 + 2 * q + 1] = ffma2(h3, wq.y, acc[3 * 8 + 2 * q + 1]);
        }
    }
    const float s1 = 0.35355339059327373f;
    #pragma unroll
    for (int t = 0; t < 32; t++) {
        float v0, v1; up2(acc[t], v0, v1);
        int ee = t >> 3, op = t & 7;
        hr[ee * 16 + 2 * op + 0] = sspf(v0 * s1);
        hr[ee * 16 + 2 * op + 1] = sspf(v1 * s1);
    }
    __syncthreads();
    #pragma unroll
    for (int o = 0; o < 16; o++)
        *(float4*)&buf[(wid * 16 + o) * 128 + lane * 4] =
            make_float4(hr[o], hr[16 + o], hr[32 + o], hr[48 + o]);
    __syncthreads();

    // ----- layer 2 -----
    #pragma unroll
    for (int t = 0; t < 32; t++) acc[t] = 0ull;
    #pragma unroll 4
    for (int j = 0; j < 64; j++) {
        float4 hv = *(const float4*)&buf[j * 128 + lane * 4];
        u64 h0 = pk2(hv.x, hv.x), h1 = pk2(hv.y, hv.y);
        u64 h2 = pk2(hv.z, hv.z), h3 = pk2(hv.w, hv.w);
        #pragma unroll
        for (int q = 0; q < 4; q++) {
            ulonglong2 wq = w2u[j * 16 + wid * 4 + q];
            acc[0 * 8 + 2 * q + 0] = ffma2(h0, wq.x, acc[0 * 8 + 2 * q + 0]);
            acc[0 * 8 + 2 * q + 1] = ffma2(h0, wq.y, acc[0 * 8 + 2 * q + 1]);
            acc[1 * 8 + 2 * q + 0] = ffma2(h1, wq.x, acc[1 * 8 + 2 * q + 0]);
            acc[1 * 8 + 2 * q + 1] = ffma2(h1, wq.y, acc[1 * 8 + 2 * q + 1]);
            acc[2 * 8 + 2 * q + 0] = ffma2(h2, wq.x, acc[2 * 8 + 2 * q + 0]);
            acc[2 * 8 + 2 * q + 1] = ffma2(h2, wq.y, acc[2 * 8 + 2 * q + 1]);
            acc[3 * 8 + 2 * q + 0] = ffma2(h3, wq.x, acc[3 * 8 + 2 * q + 0]);
            acc[3 * 8 + 2 * q + 1] = ffma2(h3, wq.y, acc[3 * 8 + 2 * q + 1]);
        }
    }
    #pragma unroll
    for (int t = 0; t < 32; t++) {
        float v0, v1; up2(acc[t], v0, v1);
        int ee = t >> 3, op = t & 7;
        hr[ee * 16 + 2 * op + 0] = sspf(v0 * 0.125f);
        hr[ee * 16 + 2 * op + 1] = sspf(v1 * 0.125f);
    }
    __syncthreads();
    #pragma unroll
    for (int o = 0; o < 16; o++)
        *(float4*)&buf[(wid * 16 + o) * 128 + lane * 4] =
            make_float4(hr[o], hr[16 + o], hr[32 + o], hr[48 + o]);
    __syncthreads();

    // ----- layer 3: outs [wid*12, +12), edges lane+32k (strided) -----
    u64 a3[24];
    #pragma unroll
    for (int t = 0; t < 24; t++) a3[t] = 0ull;
    #pragma unroll 4
    for (int j = 0; j < 64; j++) {
        u64 h0 = pk2(buf[j * 128 + lane +  0], buf[j * 128 + lane +  0]);
        u64 h1 = pk2(buf[j * 128 + lane + 32], buf[j * 128 + lane + 32]);
        u64 h2 = pk2(buf[j * 128 + lane + 64], buf[j * 128 + lane + 64]);
        u64 h3 = pk2(buf[j * 128 + lane + 96], buf[j * 128 + lane + 96]);
        #pragma unroll
        for (int q = 0; q < 3; q++) {
            ulonglong2 wq = w3u[j * 12 + wid * 3 + q];
            a3[0 * 6 + 2 * q + 0] = ffma2(h0, wq.x, a3[0 * 6 + 2 * q + 0]);
            a3[0 * 6 + 2 * q + 1] = ffma2(h0, wq.y, a3[0 * 6 + 2 * q + 1]);
            a3[1 * 6 + 2 * q + 0] = ffma2(h1, wq.x, a3[1 * 6 + 2 * q + 0]);
            a3[1 * 6 + 2 * q + 1] = ffma2(h1, wq.y, a3[1 * 6 + 2 * q + 1]);
            a3[2 * 6 + 2 * q + 0] = ffma2(h2, wq.x, a3[2 * 6 + 2 * q + 0]);
            a3[2 * 6 + 2 * q + 1] = ffma2(h2, wq.y, a3[2 * 6 + 2 * q + 1]);
            a3[3 * 6 + 2 * q + 0] = ffma2(h3, wq.x, a3[3 * 6 + 2 * q + 0]);
            a3[3 * 6 + 2 * q + 1] = ffma2(h3, wq.y, a3[3 * 6 + 2 * q + 1]);
        }
    }
    __syncthreads();   // all weight/buf reads done; pool is reusable

    // ----- bridge: wst[edge][13 f4], rot-swizzled (conflict-free) -----
    // key pre-reduced mod 13 so one conditional subtract is exact.
    float4* wstq = (float4*)pool;
    #pragma unroll
    for (int k = 0; k < 4; k++) {
        int el = lane + 32 * k;
        int keyw = (3 * (el >> 3)) % 13;   // 0..12
        #pragma unroll
        for (int q = 0; q < 3; q++) {
            float p0, p1, p2, p3;
            up2(a3[k * 6 + 2 * q + 0], p0, p1);
            up2(a3[k * 6 + 2 * q + 1], p2, p3);
            int rot = wid * 3 + q + keyw;          // <= 11 + 12 = 23
            if (rot >= 13) rot -= 13;
            wstq[el * 13 + rot] =
                make_float4(p0 * 0.125f, p1 * 0.125f, p2 * 0.125f, p3 * 0.125f);
        }
    }

    // ----- f9 and packed Sv -----
    float f9[9];
    #pragma unroll
    for (int b = 0; b < 9; b++)
        f9[b] = valid ? __ldg(&fsph[(size_t)ec * 9 + b]) : 0.0f;

    u64 svp[36];        // [a][4 d-pairs]
    float sv8[9];       // d = 8 tail
    #pragma unroll
    for (int t = 0; t < 36; t++) svp[t] = 0ull;
    #pragma unroll
    for (int a = 0; a < 9; a++) sv8[a] = 0.f;
    #pragma unroll
    for (int a = 0; a < 9; a++) {
        #pragma unroll
        for (int b = 0; b < 9; b++) {
            float fb = f9[b];
            u64 fb2 = pk2(fb, fb);
            const float4* tp = (const float4*)&Tsh[(a * 9 + b) * 12];
            float4 t0 = tp[0];
            float4 t1 = tp[1];
            float  t2 = Tsh[(a * 9 + b) * 12 + 8];
            svp[a * 4 + 0] = ffma2(fb2, pk2(t0.x, t0.y), svp[a * 4 + 0]);
            svp[a * 4 + 1] = ffma2(fb2, pk2(t0.z, t0.w), svp[a * 4 + 1]);
            svp[a * 4 + 2] = ffma2(fb2, pk2(t1.x, t1.y), svp[a * 4 + 2]);
            svp[a * 4 + 3] = ffma2(fb2, pk2(t1.z, t1.w), svp[a * 4 + 3]);
            sv8[a] = fmaf(fb, t2, sv8[a]);
        }
    }
    __syncthreads();   // wst visible to all warps

    const float4* xq4 = (const float4*)(x + (size_t)src * 144);
    float* fbufw = pool + FBUF_OFF + wid * 1152;        // 32 rows x 36 floats
    float* fbrow = fbufw + lane * 36;
    const int keyf = 2 * (lane >> 3);                   // 0..6, safe
    const int keyr = (3 * (tid >> 3)) % 13;             // 0..12, pre-reduced

    // aw pair pointers (8B-aligned: rows of 12 floats)
    const u64* aw0 = (const u64*)&awp[0];
    const u64* aw1 = (const u64*)&awp[12];
    const u64* aw2 = (const u64*)&awp[24];

    // ----- message: 4 chunks of 4 muls (36 floats each) -----
    #pragma unroll 1
    for (int c = 0; c < 4; c++) {
        float xf[36];
        if (valid) {
            #pragma unroll
            for (int q = 0; q < 9; q++) {
                float4 v = __ldg(&xq4[c * 9 + q]);
                xf[q * 4 + 0] = v.x; xf[q * 4 + 1] = v.y;
                xf[q * 4 + 2] = v.z; xf[q * 4 + 3] = v.w;
            }
        } else {
            #pragma unroll
            for (int q = 0; q < 36; q++) xf[q] = 0.f;
        }
        float wf[12];
        #pragma unroll
        for (int q = 0; q < 3; q++) {
            int rot = c * 3 + q + keyr;            // <= 11 + 12 = 23
            if (rot >= 13) rot -= 13;
            float4 v = wstq[tid * 13 + rot];
            wf[q * 4 + 0] = v.x; wf[q * 4 + 1] = v.y;
            wf[q * 4 + 2] = v.z; wf[q * 4 + 3] = v.w;
        }

        // compute + stage this chunk's 36 outputs (packed pairs, swizzled STS)
        #pragma unroll
        for (int m = 0; m < 4; m++) {
            u64 mp[4];
            mp[0] = 0ull; mp[1] = 0ull; mp[2] = 0ull; mp[3] = 0ull;
            float m8 = 0.f;
            #pragma unroll
            for (int a = 0; a < 9; a++) {
                float xv = xf[m * 9 + a];
                u64 xp = pk2(xv, xv);
                mp[0] = ffma2(xp, svp[a * 4 + 0], mp[0]);
                mp[1] = ffma2(xp, svp[a * 4 + 1], mp[1]);
                mp[2] = ffma2(xp, svp[a * 4 + 2], mp[2]);
                mp[3] = ffma2(xp, svp[a * 4 + 3], mp[3]);
                m8 = fmaf(xv, sv8[a], m8);
            }
            u64 w0p = pk2(wf[m * 3 + 0], wf[m * 3 + 0]);
            u64 w1p = pk2(wf[m * 3 + 1], wf[m * 3 + 1]);
            u64 w2p = pk2(wf[m * 3 + 2], wf[m * 3 + 2]);
            #pragma unroll
            for (int p = 0; p < 4; p++) {
                u64 facp = ffma2(w2p, aw2[p],
                           ffma2(w1p, aw1[p], mul2(w0p, aw0[p])));
                u64 rp = mul2(mp[p], facp);
                float r0, r1; up2(rp, r0, r1);
                {   // element m*9 + 2p
                    const int el = m * 9 + 2 * p;
                    int pq = (el >> 2) + keyf; if (pq >= 9) pq -= 9;
                    fbrow[pq * 4 + (el & 3)] = r0;
                }
                {   // element m*9 + 2p + 1
                    const int el = m * 9 + 2 * p + 1;
                    int pq = (el >> 2) + keyf; if (pq >= 9) pq -= 9;
                    fbrow[pq * 4 + (el & 3)] = r1;
                }
            }
            {   // element m*9 + 8 (d = 8 tail)
                float fac8 = wf[m * 3 + 0] * awp[8]
                           + wf[m * 3 + 1] * awp[20]
                           + wf[m * 3 + 2] * awp[32];
                const int el = m * 9 + 8;
                int pq = (el >> 2) + keyf; if (pq >= 9) pq -= 9;
                fbrow[pq * 4 + (el & 3)] = m8 * fac8;
            }
        }
        __syncwarp();

        // cooperative flush: 4 groups of 8 edges; 4 lanes contiguous per edge
        #pragma unroll
        for (int g = 0; g < 4; g++) {
            int owner = 8 * g + (lane >> 2);
            int dste  = __shfl_sync(0xffffffffu, dst, owner);
            int ve    = __shfl_sync(0xffffffffu, valid, owner);
            const float* sb = fbufw + owner * 36;
            float* ob = out + (size_t)dste * 144 + c * 36;
            #pragma unroll
            for (int r4 = 0; r4 < 2; r4++) {
                int q = r4 * 4 + (lane & 3);
                int pq = q + 2 * g; if (pq >= 9) pq -= 9;
                float4 v = *(const float4*)&sb[pq * 4];
                if (ve)
                    asm volatile("red.global.add.v4.f32 [%0], {%1, %2, %3, %4};"
                                 :: "l"(ob + q * 4),
                                    "f"(v.x), "f"(v.y), "f"(v.z), "f"(v.w)
                                 : "memory");
            }
            if ((lane & 3) == 0) {
                int pq = 8 + 2 * g; if (pq >= 9) pq -= 9;
                float4 v = *(const float4*)&sb[pq * 4];
                if (ve)
                    asm volatile("red.global.add.v4.f32 [%0], {%1, %2, %3, %4};"
                                 :: "l"(ob + 32),
                                    "f"(v.x), "f"(v.y), "f"(v.z), "f"(v.w)
                                 : "memory");
            }
        }
        __syncwarp();
    }
}

// ---------------------------------------------------------------------------
// kernel_launch
// inputs: 0:x 1:filter_sph 2:weight_in 3:edge_idx 4:Ux_re 5:Ux_im 6:Uf_re
//         7:Uf_im 8:Vout_re 9:Vout_im 10:W1 11:W2 12:W3 13:a_w 14:denominator
// ---------------------------------------------------------------------------
extern "C" void kernel_launch(void* const* d_in, const int* in_sizes, int n_in,
                              void* d_out, int out_size) {
    const float* x    = (const float*)d_in[0];
    const float* fsph = (const float*)d_in[1];
    const float* win  = (const float*)d_in[2];
    const int*   eidx = (const int*)  d_in[3];
    const float* Uxr  = (const float*)d_in[4];
    const float* Uxi  = (const float*)d_in[5];
    const float* Ufr  = (const float*)d_in[6];
    const float* Ufi  = (const float*)d_in[7];
    const float* Vr   = (const float*)d_in[8];
    const float* Vi   = (const float*)d_in[9];
    const float* W1   = (const float*)d_in[10];
    const float* W2   = (const float*)d_in[11];
    const float* W3   = (const float*)d_in[12];
    const float* aw   = (const float*)d_in[13];
    const float* den  = (const float*)d_in[14];
    float* out = (float*)d_out;

    int E = in_sizes[1] / 9;      // filter_sph is [E, 9]
    int n4 = out_size / 4;

    static int attr_set = 0;
    if (!attr_set) {
        cudaFuncSetAttribute(kfuse, cudaFuncAttributeMaxDynamicSharedMemorySize,
                             POOL_FLOATS * (int)sizeof(float));
        attr_set = 1;
    }

    kprep<<<(n4 + 255) / 256, 256>>>(Uxr, Uxi, Ufr, Ufi, Vr, Vi, den,
                                     (float4*)out, n4);
    kfuse<<<(E + 127) / 128, 128, POOL_FLOATS * sizeof(float)>>>(
        win, fsph, eidx, W1, W2, W3, aw, x, out, E);
}

// round 15
// speedup vs baseline: 1.0751x; 1.0751x over previous
#include <cuda_runtime.h>

// Problem constants (fixed shapes for this problem)
#define NEDGE 160000

// Scratch (static device arrays — cudaMalloc is forbidden)
__device__ __align__(16) float g_T[972];   // T[(a*9+b)*12 + d], pad 12

typedef unsigned long long u64;

// ---------------------------------------------------------------------------
// packed f32x2 helpers (Blackwell FFMA2)
// ---------------------------------------------------------------------------
__device__ __forceinline__ u64 pk2(float x, float y) {
    u64 r; asm("mov.b64 %0, {%1, %2};" : "=l"(r) : "f"(x), "f"(y)); return r;
}
__device__ __forceinline__ void up2(u64 v, float& x, float& y) {
    asm("mov.b64 {%0, %1}, %2;" : "=f"(x), "=f"(y) : "l"(v));
}
__device__ __forceinline__ u64 ffma2(u64 a, u64 b, u64 c) {
    u64 d; asm("fma.rn.f32x2 %0, %1, %2, %3;" : "=l"(d) : "l"(a), "l"(b), "l"(c));
    return d;
}

__device__ __forceinline__ float sspf(float x) {
    float e = __expf(-fabsf(x));
    return fmaxf(x, 0.0f) + __logf(1.0f + e) - 0.69314718055994531f;
}

// ---------------------------------------------------------------------------
// gridval: real 9x9 grid value of one spherical basis vector through
// pad -> ifftshift -> truncate -> irfft2 (numpy Im(DC)-dropped convention)
// ---------------------------------------------------------------------------
__device__ __forceinline__ float gridval(const float* __restrict__ Ur,
                                         const float* __restrict__ Ui,
                                         int a, int s, int t,
                                         const float* C, const float* S) {
    float acc = 0.0f;
    #pragma unroll
    for (int v = 0; v < 5; v++) {
        float gr = 0.0f, gi = 0.0f;
        int jj = (v + 4) % 9 - 2;                 // padded col -> U col
        if (jj >= 0 && jj < 5) {
            #pragma unroll
            for (int u = 0; u < 9; u++) {
                int ii = (u + 4) % 9 - 2;         // padded row -> U row
                if (ii >= 0 && ii < 5) {
                    float cr = Ur[a * 25 + ii * 5 + jj];
                    float ci = Ui[a * 25 + ii * 5 + jj];
                    int k = (u * s) % 9;
                    gr += cr * C[k] - ci * S[k];
                    gi += cr * S[k] + ci * C[k];
                }
            }
        }
        if (v == 0) {
            acc += gr;                             // Im(DC) dropped
        } else {
            int k2 = (v * t) % 9;
            acc += 2.0f * (gr * C[k2] - gi * S[k2]);
        }
    }
    return acc * (1.0f / 81.0f);
}

// ---------------------------------------------------------------------------
// kprep: all blocks zero the output (1024 threads); block 0 additionally
// builds T in a SINGLE pass (729 active threads instead of 3 serial passes).
// ---------------------------------------------------------------------------
__global__ void __launch_bounds__(1024) kprep(
    const float* __restrict__ Uxr, const float* __restrict__ Uxi,
    const float* __restrict__ Ufr, const float* __restrict__ Ufi,
    const float* __restrict__ Vr,  const float* __restrict__ Vi,
    const float* __restrict__ denom,
    float4* __restrict__ o4, int n4) {
    __shared__ float C9[9], S9[9];
    __shared__ float Gx[729], Gf[729], Pm[729];

    int tid = threadIdx.x;
    int i = blockIdx.x * 1024 + tid;
    if (i < n4) o4[i] = make_float4(0.f, 0.f, 0.f, 0.f);

    if (blockIdx.x != 0) return;

    if (tid < 9) {
        double ang = 2.0 * 3.14159265358979323846 * (double)tid / 9.0;
        C9[tid] = (float)cos(ang);
        S9[tid] = (float)sin(ang);
    }
    __syncthreads();
    if (tid < 729) {
        {   // grid bases: tid = a*81 + s*9 + t
            int a = tid / 81, s = (tid / 9) % 9, t = tid % 9;
            Gx[tid] = gridval(Uxr, Uxi, a, s, t, C9, S9);
            Gf[tid] = gridval(Ufr, Ufi, a, s, t, C9, S9);
        }
        {   // projection: tid = (s*9+t)*9 + d
            int st = tid / 9, d = tid % 9;
            int s = st / 9, t = st % 9;
            float p = 0.0f;
            #pragma unroll
            for (int u = 0; u < 9; u++)
                #pragma unroll
                for (int k = 0; k < 5; k++) {
                    int th = (u * s + k * t) % 9;
                    p += Vr[u * 45 + k * 9 + d] * C9[th]
                       + Vi[u * 45 + k * 9 + d] * S9[th];
                }
            Pm[tid] = p;
        }
    }
    __syncthreads();
    if (tid < 729) {
        float inv = 1.0f / denom[0];
        int a = tid / 81, b = (tid / 9) % 9, d = tid % 9;
        float acc = 0.0f;
        #pragma unroll 9
        for (int st = 0; st < 81; st++)
            acc += Gx[a * 81 + st] * Gf[b * 81 + st] * Pm[st * 9 + d];
        g_T[(a * 9 + b) * 12 + d] = acc * inv;
    }
}

// ---------------------------------------------------------------------------
// kfuse: fused block-tiled MLP + message + scatter. 128 threads = 128 edges.
// (R12 form — best measured: kfuse 103.6 us.)
//   MLP tiled as GEMM: warp wid owns an output slice, lane owns 4 edges;
//   activations transposed through a shared hT[64][128] buffer so weight
//   reads are per-warp-distinct (weights read ONCE per block, not per warp).
//   Dynamic smem pool (63.5 KB) phase-aliased:
//     phase A (MLP):    [w1 512 | w2 4096 | w3 3072 | hT 8192]      floats
//     phase B (message):[wst 6656 (stride 52) | fbuf 4608]          floats
// ---------------------------------------------------------------------------
#define POOL_FLOATS 15872
#define BUF_OFF 7680
#define FBUF_OFF 6656

__global__ void __launch_bounds__(128, 3) kfuse(
    const float* __restrict__ win,
    const float* __restrict__ fsph,
    const int*   __restrict__ eidx,
    const float* __restrict__ W1,
    const float* __restrict__ W2,
    const float* __restrict__ W3,
    const float* __restrict__ aw,
    const float* __restrict__ x,
    float* __restrict__ out,
    int E) {
    extern __shared__ __align__(16) float pool[];
    __shared__ __align__(16) float Tsh[972];
    __shared__ float awsh[27];

    const int tid  = threadIdx.x;
    const int wid  = tid >> 5;
    const int lane = tid & 31;

    // ---- stage weights (coalesced, once per block) + T + aw ----
    float4* p4 = (float4*)pool;
    p4[tid] = ((const float4*)W1)[tid];                       // 512 f @ 0
    #pragma unroll
    for (int i = 0; i < 8; i++)                               // 4096 f @ 512
        p4[128 + tid + i * 128] = ((const float4*)W2)[tid + i * 128];
    #pragma unroll
    for (int i = 0; i < 6; i++)                               // 3072 f @ 4608
        p4[1152 + tid + i * 128] = ((const float4*)W3)[tid + i * 128];
    #pragma unroll
    for (int i = 0; i < 8; i++) {
        int idx = tid + i * 128;
        if (idx < 972) Tsh[idx] = g_T[idx];
    }
    if (tid < 27) awsh[tid] = aw[tid];

    // ---- per-thread message-edge metadata + win -> wiT (buf rows 0..7) ----
    int e = blockIdx.x * 128 + tid;
    int valid = (e < E) ? 1 : 0;
    int ec = valid ? e : 0;
    int dst = __ldg(&eidx[ec]);
    int src = __ldg(&eidx[E + ec]);

    float* buf = pool + BUF_OFF;
    {
        float4 wa = __ldg(&((const float4*)win)[(size_t)ec * 2 + 0]);
        float4 wb = __ldg(&((const float4*)win)[(size_t)ec * 2 + 1]);
        buf[0 * 128 + tid] = wa.x; buf[1 * 128 + tid] = wa.y;
        buf[2 * 128 + tid] = wa.z; buf[3 * 128 + tid] = wa.w;
        buf[4 * 128 + tid] = wb.x; buf[5 * 128 + tid] = wb.y;
        buf[6 * 128 + tid] = wb.z; buf[7 * 128 + tid] = wb.w;
    }
    __syncthreads();

    const ulonglong2* w1u = (const ulonglong2*)pool;            // 128 u2
    const ulonglong2* w2u = (const ulonglong2*)(pool + 512);    // 1024 u2
    const ulonglong2* w3u = (const ulonglong2*)(pool + 4608);   // 768 u2

    u64 acc[32];        // [4 edges][8 outpairs]
    float hr[64];       // [4 edges][16 outs]

    // ----- layer 1: outs [wid*16, +16), edges lane*4..+3 -----
    #pragma unroll
    for (int t = 0; t < 32; t++) acc[t] = 0ull;
    #pragma unroll
    for (int i = 0; i < 8; i++) {
        float4 hv = *(const float4*)&buf[i * 128 + lane * 4];
        u64 h0 = pk2(hv.x, hv.x), h1 = pk2(hv.y, hv.y);
        u64 h2 = pk2(hv.z, hv.z), h3 = pk2(hv.w, hv.w);
        #pragma unroll
        for (int q = 0; q < 4; q++) {
            ulonglong2 wq = w1u[i * 16 + wid * 4 + q];
            acc[0 * 8 + 2 * q + 0] = ffma2(h0, wq.x, acc[0 * 8 + 2 * q + 0]);
            acc[0 * 8 + 2 * q + 1] = ffma2(h0, wq.y, acc[0 * 8 + 2 * q + 1]);
            acc[1 * 8 + 2 * q + 0] = ffma2(h1, wq.x, acc[1 * 8 + 2 * q + 0]);
            acc[1 * 8 + 2 * q + 1] = ffma2(h1, wq.y, acc[1 * 8 + 2 * q + 1]);
            acc[2 * 8 + 2 * q + 0] = ffma2(h2, wq.x, acc[2 * 8 + 2 * q + 0]);
            acc[2 * 8 + 2 * q + 1] = ffma2(h2, wq.y, acc[2 * 8 + 2 * q + 1]);
            acc[3 * 8 + 2 * q + 0] = ffma2(h3, wq.x, acc[3 * 8 + 2 * q + 0]);
            acc[3 * 8 + 2 * q + 1] = ffma2(h3, wq.y, acc[3 * 8 + 2 * q + 1]);
        }
    }
    const float s1 = 0.35355339059327373f;
    #pragma unroll
    for (int t = 0; t < 32; t++) {
        float v0, v1; up2(acc[t], v0, v1);
        int ee = t >> 3, op = t & 7;
        hr[ee * 16 + 2 * op + 0] = sspf(v0 * s1);
        hr[ee * 16 + 2 * op + 1] = sspf(v1 * s1);
    }
    __syncthreads();
    #pragma unroll
    for (int o = 0; o < 16; o++)
        *(float4*)&buf[(wid * 16 + o) * 128 + lane * 4] =
            make_float4(hr[o], hr[16 + o], hr[32 + o], hr[48 + o]);
    __syncthreads();

    // ----- layer 2 -----
    #pragma unroll
    for (int t = 0; t < 32; t++) acc[t] = 0ull;
    #pragma unroll 4
    for (int j = 0; j < 64; j++) {
        float4 hv = *(const float4*)&buf[j * 128 + lane * 4];
        u64 h0 = pk2(hv.x, hv.x), h1 = pk2(hv.y, hv.y);
        u64 h2 = pk2(hv.z, hv.z), h3 = pk2(hv.w, hv.w);
        #pragma unroll
        for (int q = 0; q < 4; q++) {
            ulonglong2 wq = w2u[j * 16 + wid * 4 + q];
            acc[0 * 8 + 2 * q + 0] = ffma2(h0, wq.x, acc[0 * 8 + 2 * q + 0]);
            acc[0 * 8 + 2 * q + 1] = ffma2(h0, wq.y, acc[0 * 8 + 2 * q + 1]);
            acc[1 * 8 + 2 * q + 0] = ffma2(h1, wq.x, acc[1 * 8 + 2 * q + 0]);
            acc[1 * 8 + 2 * q + 1] = ffma2(h1, wq.y, acc[1 * 8 + 2 * q + 1]);
            acc[2 * 8 + 2 * q + 0] = ffma2(h2, wq.x, acc[2 * 8 + 2 * q + 0]);
            acc[2 * 8 + 2 * q + 1] = ffma2(h2, wq.y, acc[2 * 8 + 2 * q + 1]);
            acc[3 * 8 + 2 * q + 0] = ffma2(h3, wq.x, acc[3 * 8 + 2 * q + 0]);
            acc[3 * 8 + 2 * q + 1] = ffma2(h3, wq.y, acc[3 * 8 + 2 * q + 1]);
        }
    }
    #pragma unroll
    for (int t = 0; t < 32; t++) {
        float v0, v1; up2(acc[t], v0, v1);
        int ee = t >> 3, op = t & 7;
        hr[ee * 16 + 2 * op + 0] = sspf(v0 * 0.125f);
        hr[ee * 16 + 2 * op + 1] = sspf(v1 * 0.125f);
    }
    __syncthreads();
    #pragma unroll
    for (int o = 0; o < 16; o++)
        *(float4*)&buf[(wid * 16 + o) * 128 + lane * 4] =
            make_float4(hr[o], hr[16 + o], hr[32 + o], hr[48 + o]);
    __syncthreads();

    // ----- layer 3: outs [wid*12, +12), edges lane+32k (strided) -----
    u64 a3[24];
    #pragma unroll
    for (int t = 0; t < 24; t++) a3[t] = 0ull;
    #pragma unroll 4
    for (int j = 0; j < 64; j++) {
        u64 h0 = pk2(buf[j * 128 + lane +  0], buf[j * 128 + lane +  0]);
        u64 h1 = pk2(buf[j * 128 + lane + 32], buf[j * 128 + lane + 32]);
        u64 h2 = pk2(buf[j * 128 + lane + 64], buf[j * 128 + lane + 64]);
        u64 h3 = pk2(buf[j * 128 + lane + 96], buf[j * 128 + lane + 96]);
        #pragma unroll
        for (int q = 0; q < 3; q++) {
            ulonglong2 wq = w3u[j * 12 + wid * 3 + q];
            a3[0 * 6 + 2 * q + 0] = ffma2(h0, wq.x, a3[0 * 6 + 2 * q + 0]);
            a3[0 * 6 + 2 * q + 1] = ffma2(h0, wq.y, a3[0 * 6 + 2 * q + 1]);
            a3[1 * 6 + 2 * q + 0] = ffma2(h1, wq.x, a3[1 * 6 + 2 * q + 0]);
            a3[1 * 6 + 2 * q + 1] = ffma2(h1, wq.y, a3[1 * 6 + 2 * q + 1]);
            a3[2 * 6 + 2 * q + 0] = ffma2(h2, wq.x, a3[2 * 6 + 2 * q + 0]);
            a3[2 * 6 + 2 * q + 1] = ffma2(h2, wq.y, a3[2 * 6 + 2 * q + 1]);
            a3[3 * 6 + 2 * q + 0] = ffma2(h3, wq.x, a3[3 * 6 + 2 * q + 0]);
            a3[3 * 6 + 2 * q + 1] = ffma2(h3, wq.y, a3[3 * 6 + 2 * q + 1]);
        }
    }
    __syncthreads();   // all weight/buf reads done; pool is reusable

    // ----- bridge: wst[edge][13 f4] (stride 52 floats = bandwidth-minimal) --
    float4* wstq = (float4*)pool;
    #pragma unroll
    for (int k = 0; k < 4; k++) {
        int el = lane + 32 * k;
        #pragma unroll
        for (int q = 0; q < 3; q++) {
            float p0, p1, p2, p3;
            up2(a3[k * 6 + 2 * q + 0], p0, p1);
            up2(a3[k * 6 + 2 * q + 1], p2, p3);
            wstq[el * 13 + wid * 3 + q] =
                make_float4(p0 * 0.125f, p1 * 0.125f, p2 * 0.125f, p3 * 0.125f);
        }
    }

    // ----- f9 and Sv (register-resident, per message edge = tid) -----
    float f9[9];
    #pragma unroll
    for (int b = 0; b < 9; b++)
        f9[b] = valid ? __ldg(&fsph[(size_t)ec * 9 + b]) : 0.0f;

    float Sv[81];
    #pragma unroll
    for (int a = 0; a < 9; a++) {
        float s0x = 0.f, s0y = 0.f, s0z = 0.f, s0w = 0.f;
        float s1x = 0.f, s1y = 0.f, s1z = 0.f, s1w = 0.f;
        float s2 = 0.f;
        #pragma unroll
        for (int b = 0; b < 9; b++) {
            float fb = f9[b];
            const float4* tp = (const float4*)&Tsh[(a * 9 + b) * 12];
            float4 t0 = tp[0];
            float4 t1 = tp[1];
            float  t2 = Tsh[(a * 9 + b) * 12 + 8];
            s0x += fb * t0.x; s0y += fb * t0.y; s0z += fb * t0.z; s0w += fb * t0.w;
            s1x += fb * t1.x; s1y += fb * t1.y; s1z += fb * t1.z; s1w += fb * t1.w;
            s2  += fb * t2;
        }
        Sv[a * 9 + 0] = s0x; Sv[a * 9 + 1] = s0y; Sv[a * 9 + 2] = s0z; Sv[a * 9 + 3] = s0w;
        Sv[a * 9 + 4] = s1x; Sv[a * 9 + 5] = s1y; Sv[a * 9 + 6] = s1z; Sv[a * 9 + 7] = s1w;
        Sv[a * 9 + 8] = s2;
    }
    __syncthreads();   // wst visible to all warps

    const float4* xq4 = (const float4*)(x + (size_t)src * 144);
    float* fbufw = pool + FBUF_OFF + wid * 1152;        // 32 rows x 36 floats
    float4* fb = (float4*)(fbufw + lane * 36);          // 16B-aligned

    // ----- message: 4 chunks of 4 muls (36 floats each) -----
    #pragma unroll 1
    for (int c = 0; c < 4; c++) {
        float xf[36];
        if (valid) {
            #pragma unroll
            for (int q = 0; q < 9; q++) {
                float4 v = __ldg(&xq4[c * 9 + q]);
                xf[q * 4 + 0] = v.x; xf[q * 4 + 1] = v.y;
                xf[q * 4 + 2] = v.z; xf[q * 4 + 3] = v.w;
            }
        } else {
            #pragma unroll
            for (int q = 0; q < 36; q++) xf[q] = 0.f;
        }
        float wf[12];
        #pragma unroll
        for (int q = 0; q < 3; q++) {
            float4 v = wstq[tid * 13 + c * 3 + q];
            wf[q * 4 + 0] = v.x; wf[q * 4 + 1] = v.y;
            wf[q * 4 + 2] = v.z; wf[q * 4 + 3] = v.w;
        }

        // compute + stage this chunk's 36 outputs
        #pragma unroll
        for (int q = 0; q < 9; q++) {
            float r[4];
            #pragma unroll
            for (int i = 0; i < 4; i++) {
                const int cf = q * 4 + i;
                const int mm = cf / 9;
                const int d  = cf % 9;
                float s = 0.f;
                #pragma unroll
                for (int a = 0; a < 9; a++) s += xf[mm * 9 + a] * Sv[a * 9 + d];
                float fac = wf[mm * 3 + 0] * awsh[d]
                          + wf[mm * 3 + 1] * awsh[9 + d]
                          + wf[mm * 3 + 2] * awsh[18 + d];
                r[i] = s * fac;
            }
            fb[q] = make_float4(r[0], r[1], r[2], r[3]);
        }
        __syncwarp();

        // cooperative flush: 4 groups of 8 edges; 4 lanes contiguous per edge
        #pragma unroll
        for (int g = 0; g < 4; g++) {
            int owner = 8 * g + (lane >> 2);
            int dste  = __shfl_sync(0xffffffffu, dst, owner);
            int ve    = __shfl_sync(0xffffffffu, valid, owner);
            const float4* sb = (const float4*)(fbufw + owner * 36);
            float* ob = out + (size_t)dste * 144 + c * 36;
            #pragma unroll
            for (int r4 = 0; r4 < 2; r4++) {
                int q = r4 * 4 + (lane & 3);
                float4 v = sb[q];
                if (ve)
                    asm volatile("red.global.add.v4.f32 [%0], {%1, %2, %3, %4};"
                                 :: "l"(ob + q * 4),
                                    "f"(v.x), "f"(v.y), "f"(v.z), "f"(v.w)
                                 : "memory");
            }
            if ((lane & 3) == 0) {
                float4 v = sb[8];
                if (ve)
                    asm volatile("red.global.add.v4.f32 [%0], {%1, %2, %3, %4};"
                                 :: "l"(ob + 32),
                                    "f"(v.x), "f"(v.y), "f"(v.z), "f"(v.w)
                                 : "memory");
            }
        }
        __syncwarp();
    }
}

// ---------------------------------------------------------------------------
// kernel_launch
// inputs: 0:x 1:filter_sph 2:weight_in 3:edge_idx 4:Ux_re 5:Ux_im 6:Uf_re
//         7:Uf_im 8:Vout_re 9:Vout_im 10:W1 11:W2 12:W3 13:a_w 14:denominator
// ---------------------------------------------------------------------------
extern "C" void kernel_launch(void* const* d_in, const int* in_sizes, int n_in,
                              void* d_out, int out_size) {
    const float* x    = (const float*)d_in[0];
    const float* fsph = (const float*)d_in[1];
    const float* win  = (const float*)d_in[2];
    const int*   eidx = (const int*)  d_in[3];
    const float* Uxr  = (const float*)d_in[4];
    const float* Uxi  = (const float*)d_in[5];
    const float* Ufr  = (const float*)d_in[6];
    const float* Ufi  = (const float*)d_in[7];
    const float* Vr   = (const float*)d_in[8];
    const float* Vi   = (const float*)d_in[9];
    const float* W1   = (const float*)d_in[10];
    const float* W2   = (const float*)d_in[11];
    const float* W3   = (const float*)d_in[12];
    const float* aw   = (const float*)d_in[13];
    const float* den  = (const float*)d_in[14];
    float* out = (float*)d_out;

    int E = in_sizes[1] / 9;      // filter_sph is [E, 9]
    int n4 = out_size / 4;

    static int attr_set = 0;
    if (!attr_set) {
        cudaFuncSetAttribute(kfuse, cudaFuncAttributeMaxDynamicSharedMemorySize,
                             POOL_FLOATS * (int)sizeof(float));
        attr_set = 1;
    }

    kprep<<<(n4 + 1023) / 1024, 1024>>>(Uxr, Uxi, Ufr, Ufi, Vr, Vi, den,
                                        (float4*)out, n4);
    kfuse<<<(E + 127) / 128, 128, POOL_FLOATS * sizeof(float)>>>(
        win, fsph, eidx, W1, W2, W3, aw, x, out, E);
}